// round 17
// baseline (speedup 1.0000x reference)
#include <cuda_runtime.h>
#include <cuda_fp16.h>
#include <cstdint>

#define BB 4
#define TT 4096
#define DD 768
#define HH 64
#define BT (BB*TT)
#define NSPLIT 4
#define MCONST 16.0f

// Scratch.
// g_Qh: fp16, pre-scaled (x0.125*log2e), h PAIR-PERMUTED.
// g_Kh: fp16, h PAIR-PERMUTED.
// g_Vth: fp16, transposed [b][h][t], t PAIR-PERMUTED.
// g_Wf: W pre-split tf32 (hi,lo), pre-packed in qkv's fragment layout.
__device__ __half g_Qh[BT * HH];
__device__ __half g_Kh[BT * HH];
__device__ __half g_Vth[BB * HH * TT];
__device__ float4 g_Wf[24 * 6144];
__device__ float  g_pO[NSPLIT * BT * HH];   // partial O (scale 2^-MCONST)
__device__ float  g_pl[NSPLIT * BT];        // partial denom (same scale)

// ---------------------------------------------------------------------------
// helpers
// ---------------------------------------------------------------------------
__device__ __forceinline__ uint32_t f2tf(float f) {
    uint32_t u;
    asm("cvt.rna.tf32.f32 %0, %1;" : "=r"(u) : "f"(f));
    return u;
}
__device__ __forceinline__ float tf32f(float f) {
    return __uint_as_float(f2tf(f));
}
__device__ __forceinline__ float ex2(float x) {
    float y;
    asm("ex2.approx.f32 %0, %1;" : "=f"(y) : "f"(x));
    return y;
}
__device__ __forceinline__ uint32_t pack_h2(float lo, float hi) {
    uint32_t u;
    asm("cvt.rn.f16x2.f32 %0, %1, %2;" : "=r"(u) : "f"(hi), "f"(lo));
    return u;
}

__device__ __forceinline__ void mma_tf32(float d[4], const uint32_t a[4],
                                         uint32_t b0, uint32_t b1) {
    asm volatile(
        "mma.sync.aligned.m16n8k8.row.col.f32.tf32.tf32.f32 "
        "{%0,%1,%2,%3}, {%4,%5,%6,%7}, {%8,%9}, {%0,%1,%2,%3};"
        : "+f"(d[0]), "+f"(d[1]), "+f"(d[2]), "+f"(d[3])
        : "r"(a[0]), "r"(a[1]), "r"(a[2]), "r"(a[3]), "r"(b0), "r"(b1));
}

__device__ __forceinline__ void mma_f16(float d[4], const uint32_t a[4],
                                        uint32_t b0, uint32_t b1) {
    asm volatile(
        "mma.sync.aligned.m16n8k16.row.col.f32.f16.f16.f32 "
        "{%0,%1,%2,%3}, {%4,%5,%6,%7}, {%8,%9}, {%0,%1,%2,%3};"
        : "+f"(d[0]), "+f"(d[1]), "+f"(d[2]), "+f"(d[3])
        : "r"(a[0]), "r"(a[1]), "r"(a[2]), "r"(a[3]), "r"(b0), "r"(b1));
}

__device__ __forceinline__ void cpa16(uint32_t smem_dst, const void* gsrc) {
    asm volatile("cp.async.cg.shared.global [%0], [%1], 16;"
                 :: "r"(smem_dst), "l"(gsrc));
}
__device__ __forceinline__ void cpa_commit() {
    asm volatile("cp.async.commit_group;");
}
__device__ __forceinline__ void cpa_wait0() {
    asm volatile("cp.async.wait_group 0;" ::: "memory");
}
__device__ __forceinline__ void cpa_wait1() {
    asm volatile("cp.async.wait_group 1;" ::: "memory");
}
__device__ __forceinline__ void cpa_wait2() {
    asm volatile("cp.async.wait_group 2;" ::: "memory");
}

// pair-permuted position for even column `col` within its 16-group
__device__ __forceinline__ int pairperm(int col) {
    const int pg = (col >> 1) & 7;
    const int np = ((pg & 3) << 1) | (pg >> 2);
    return (col & ~15) | (np << 1);
}

// ---------------------------------------------------------------------------
// Kernel 0: split W into (hi, lo) tf32 and scatter into fragment layout.
// ---------------------------------------------------------------------------
__global__ __launch_bounds__(256) void prep_w(
    const float* __restrict__ Wq, const float* __restrict__ Wk,
    const float* __restrict__ Wv)
{
    int i = blockIdx.x * 256 + threadIdx.x;
    if (i >= DD * 192) return;
    int k = i / 192, n = i % 192;
    float v = (n < 64) ? Wq[k * 64 + n]
            : (n < 128) ? Wk[k * 64 + n - 64]
            : Wv[k * 64 + n - 128];
    float hi = tf32f(v);
    float lo = tf32f(v - hi);

    const int kt   = k >> 5;
    const int kk   = k & 31;
    const int kb   = kk >> 3;
    const int kr   = kk & 7;
    const int nb   = n >> 3;
    const int lane = ((n & 7) << 2) | (kr & 3);
    const int slot = kr >> 2;
    float* dst = (float*)&g_Wf[kt * 6144 + (kb * 24 + nb) * 32 + lane];
    dst[slot]     = hi;
    dst[2 + slot] = lo;
}

// ---------------------------------------------------------------------------
// Kernel 1: QKV projection (unchanged from R16 — near memory floor).
// ---------------------------------------------------------------------------
#define QSCALE (0.125f * 1.4426950408889634f)
#define QKV_STAGE_B 43008u   // 18432 + 24576

__global__ __launch_bounds__(256, 2) void qkv_mma(const float* __restrict__ x)
{
    extern __shared__ float qsm[];

    const int tid = threadIdx.x;
    const int w   = tid >> 5;
    const int l   = tid & 31;
    const int mg  = w >> 1;
    const int ng  = w & 1;
    const int row0 = (blockIdx.x >> 1) * 128;
    const int n0   = (blockIdx.x & 1) * 96;
    const int nb0  = (blockIdx.x & 1) * 12;

    float acc[2][6][4];
    #pragma unroll
    for (int mt = 0; mt < 2; mt++)
        #pragma unroll
        for (int nb = 0; nb < 6; nb++)
            acc[mt][nb][0] = acc[mt][nb][1] = acc[mt][nb][2] = acc[mt][nb][3] = 0.0f;

    const uint32_t sb = (uint32_t)__cvta_generic_to_shared(qsm);

    const int xrow = tid >> 3;
    const int xcq  = tid & 7;

    auto issue = [&](int st, int k0) {
        const uint32_t base = sb + (uint32_t)st * QKV_STAGE_B;
        #pragma unroll
        for (int t = 0; t < 4; t++) {
            const int row = xrow + t * 32;
            cpa16(base + (uint32_t)row * 144u + (uint32_t)xcq * 16u,
                  &x[(size_t)(row0 + row) * DD + k0 + xcq * 4]);
        }
        const int kt = k0 >> 5;
        #pragma unroll
        for (int j = 0; j < 6; j++) {
            const int idx = tid + j * 256;
            const int kb  = idx / 384;
            const int off = idx - kb * 384;
            cpa16(base + 18432u + (uint32_t)idx * 16u,
                  (const char*)g_Wf + (size_t)(kt * 6144 + kb * 768 + nb0 * 32 + off) * 16);
        }
        cpa_commit();
    };

    issue(0, 0);
    int cur = 0;

    for (int k0 = 0; k0 < DD; k0 += 32) {
        cpa_wait0();
        __syncthreads();
        if (k0 + 32 < DD) issue(cur ^ 1, k0 + 32);

        const float*  xs = qsm + cur * (QKV_STAGE_B / 4);
        const float4* wf = (const float4*)(xs + 128 * 36);

        #pragma unroll
        for (int kb = 0; kb < 4; kb++) {
            uint32_t ahi[2][4];
            #pragma unroll
            for (int mt = 0; mt < 2; mt++) {
                const int rA = mg * 32 + mt * 16 + (l >> 2);
                const int cA = kb * 8 + (l & 3);
                ahi[mt][0] = f2tf(xs[rA * 36 + cA]);
                ahi[mt][1] = f2tf(xs[(rA + 8) * 36 + cA]);
                ahi[mt][2] = f2tf(xs[rA * 36 + cA + 4]);
                ahi[mt][3] = f2tf(xs[(rA + 8) * 36 + cA + 4]);
            }
            #pragma unroll
            for (int nb = 0; nb < 6; nb++) {
                float4 q = wf[(kb * 12 + ng * 6 + nb) * 32 + l];
                uint32_t bh0 = __float_as_uint(q.x), bh1 = __float_as_uint(q.y);
                uint32_t bl0 = __float_as_uint(q.z), bl1 = __float_as_uint(q.w);
                #pragma unroll
                for (int mt = 0; mt < 2; mt++) {
                    mma_tf32(acc[mt][nb], ahi[mt], bh0, bh1);
                    mma_tf32(acc[mt][nb], ahi[mt], bl0, bl1);
                }
            }
        }
        cur ^= 1;
    }

    #pragma unroll
    for (int mt = 0; mt < 2; mt++) {
        #pragma unroll
        for (int nb = 0; nb < 6; nb++) {
            const int rowa  = row0 + mg * 32 + mt * 16 + (l >> 2);
            const int nglob = n0 + ng * 48 + nb * 8 + (l & 3) * 2;
            const int mat   = nglob >> 6;
            const int col   = nglob & 63;
            if (mat == 0) {
                const int pos = pairperm(col);
                g_Qh[(size_t)rowa * HH + pos]           = __float2half_rn(QSCALE * acc[mt][nb][0]);
                g_Qh[(size_t)rowa * HH + pos + 1]       = __float2half_rn(QSCALE * acc[mt][nb][1]);
                g_Qh[(size_t)(rowa + 8) * HH + pos]     = __float2half_rn(QSCALE * acc[mt][nb][2]);
                g_Qh[(size_t)(rowa + 8) * HH + pos + 1] = __float2half_rn(QSCALE * acc[mt][nb][3]);
            } else if (mat == 1) {
                const int pos = pairperm(col);
                g_Kh[(size_t)rowa * HH + pos]           = __float2half_rn(acc[mt][nb][0]);
                g_Kh[(size_t)rowa * HH + pos + 1]       = __float2half_rn(acc[mt][nb][1]);
                g_Kh[(size_t)(rowa + 8) * HH + pos]     = __float2half_rn(acc[mt][nb][2]);
                g_Kh[(size_t)(rowa + 8) * HH + pos + 1] = __float2half_rn(acc[mt][nb][3]);
            } else {
                const int bb = rowa >> 12;
                const int t0 = rowa & 4095;
                const int q2 = (t0 >> 1) & 3;
                const int tp = (t0 & ~15) | (q2 << 2) | (t0 & 1);
                __half* v0 = g_Vth + (size_t)((bb << 6) + col) * TT;
                __half* v1 = g_Vth + (size_t)((bb << 6) + col + 1) * TT;
                v0[tp]     = __float2half_rn(acc[mt][nb][0]);
                v1[tp]     = __float2half_rn(acc[mt][nb][1]);
                v0[tp + 2] = __float2half_rn(acc[mt][nb][2]);
                v1[tp + 2] = __float2half_rn(acc[mt][nb][3]);
            }
        }
    }
}

// ---------------------------------------------------------------------------
// Kernel 2: causal flash attention, split-kv (4), fixed-max softmax,
// fp16 MMAs, BM=128 (8 warps / 256 thr) sharing 64-row K/V tiles,
// FOUR-stage cp.async pipeline (three loads in flight). 64 KB -> 2 CTAs/SM
// (4 warps/SMSP). Warp-uniform skip for fully-masked tiles.
// ---------------------------------------------------------------------------
__global__ __launch_bounds__(256, 2) void attn_kernel()
{
    extern __shared__ __half smh[];   // [4 bufs][K 4096 | V 4096] halves

    const int tid = threadIdx.x;
    const int w   = tid >> 5;         // 0..7
    const int l   = tid & 31;
    const int r   = l >> 2;
    const int c   = l & 3;

    const int bid = blockIdx.x;
    const int qt  = 31 - (bid >> 4);          // heavy q-tiles first
    const int b   = (bid >> 2) & 3;
    const int s   = bid & 3;
    const int q0  = qt * 128;
    const size_t base = (size_t)b * TT * HH;

    const int nt    = 2 * qt + 2;             // kv tiles covering [0, q0+128)
    const int chunk = (nt + NSPLIT - 1) >> 2;
    const int ktbeg = min(s * chunk, nt);
    const int ktend = min(ktbeg + chunk, nt);

    const int rowg  = q0 + w * 16 + r;
    const int rowg8 = rowg + 8;
    const int wmax  = q0 + w * 16 + 15;

    float o[8][4];
    #pragma unroll
    for (int hb = 0; hb < 8; hb++)
        o[hb][0] = o[hb][1] = o[hb][2] = o[hb][3] = 0.0f;
    float lR = 0.0f, lR8 = 0.0f;

    if (ktbeg < ktend) {
        const uint32_t sb = (uint32_t)__cvta_generic_to_shared(smh);

        // staging: 64 rows x 8 chunks per tensor, 256 threads -> 2+2 chunks
        const int crow = tid >> 3;            // 0..31 (+32)
        const int ch   = tid & 7;

        uint32_t qf[4][4];
        #pragma unroll
        for (int kb = 0; kb < 4; kb++) {
            uint2 u0 = *(const uint2*)&g_Qh[base + (size_t)rowg  * HH + kb * 16 + 4 * c];
            uint2 u1 = *(const uint2*)&g_Qh[base + (size_t)rowg8 * HH + kb * 16 + 4 * c];
            qf[kb][0] = u0.x;
            qf[kb][1] = u1.x;
            qf[kb][2] = u0.y;
            qf[kb][3] = u1.y;
        }

        auto issue = [&](int bf, int jb) {
            #pragma unroll
            for (int i = 0; i < 2; i++) {
                const int row = crow + i * 32;
                const uint32_t swz = (uint32_t)((ch ^ ((row & 3) << 1)) << 4);
                cpa16(sb + (uint32_t)bf * 16384u + (uint32_t)row * 128u + swz,
                      g_Kh + base + (size_t)(jb + row) * HH + ch * 8);
                cpa16(sb + (uint32_t)bf * 16384u + 8192u + (uint32_t)row * 128u + swz,
                      g_Vth + (size_t)((b << 6) + row) * TT + jb + ch * 8);
            }
            cpa_commit();
        };

        // prologue: up to three tiles in flight
        issue(0, ktbeg * 64);
        if (ktbeg + 1 < ktend) issue(1, (ktbeg + 1) * 64);
        if (ktbeg + 2 < ktend) issue(2, (ktbeg + 2) * 64);

        int bi = 0;
        const int rx   = (r & 3) << 1;
        const int cc   = c >> 1;
        const int hoff = (c & 1) * 4;

        for (int kt = ktbeg; kt < ktend; kt++) {
            const int jbase = kt * 64;
            if      (kt + 2 < ktend) cpa_wait2();  // tile kt done; kt+1,kt+2 in flight
            else if (kt + 1 < ktend) cpa_wait1();
            else                     cpa_wait0();
            __syncthreads();                        // all warps done with tile kt-1
            if (kt + 3 < ktend) {
                int nb3 = (bi + 3) & 3;
                issue(nb3, (kt + 3) * 64);          // overwrites tile kt-1's buffer
            }

            // warp-uniform skip: warp's rows all precede this kv tile
            if (jbase <= wmax) {
                const __half* kp = smh + bi * 8192;
                const __half* vp = kp + 4096;

                // ---- S = Q K^T (fp16 m16n8k16) ----
                float sS[8][4];
                #pragma unroll
                for (int nb = 0; nb < 8; nb++)
                    sS[nb][0] = sS[nb][1] = sS[nb][2] = sS[nb][3] = 0.0f;
                #pragma unroll
                for (int nb = 0; nb < 8; nb++) {
                    const __half* krow = kp + (nb * 8 + r) * 64;
                    #pragma unroll
                    for (int kb = 0; kb < 4; kb++) {
                        uint2 bk = *(const uint2*)&krow[(((2 * kb + cc) ^ rx) << 3) + hoff];
                        mma_f16(sS[nb], qf[kb], bk.x, bk.y);
                    }
                }

                // elementwise causal mask where the tile straddles the diagonal
                if (jbase + 63 > rowg) {
                    #pragma unroll
                    for (int nb = 0; nb < 8; nb++) {
                        const int col = jbase + nb * 8 + 2 * c;
                        if (col     > rowg ) sS[nb][0] = -1.0e30f;
                        if (col + 1 > rowg ) sS[nb][1] = -1.0e30f;
                        if (col     > rowg8) sS[nb][2] = -1.0e30f;
                        if (col + 1 > rowg8) sS[nb][3] = -1.0e30f;
                    }
                }

                // ---- fixed-max softmax: p = 2^(s - M) ----
                float sum0 = 0.0f, sum1 = 0.0f;
                #pragma unroll
                for (int nb = 0; nb < 8; nb++) {
                    sS[nb][0] = ex2(sS[nb][0] - MCONST);
                    sS[nb][1] = ex2(sS[nb][1] - MCONST);
                    sS[nb][2] = ex2(sS[nb][2] - MCONST);
                    sS[nb][3] = ex2(sS[nb][3] - MCONST);
                    sum0 += sS[nb][0] + sS[nb][1];
                    sum1 += sS[nb][2] + sS[nb][3];
                }
                lR  += sum0;
                lR8 += sum1;

                // ---- O += P @ V (fp16; direct fragment reuse) ----
                #pragma unroll
                for (int kb = 0; kb < 4; kb++) {
                    uint32_t a[4];
                    a[0] = pack_h2(sS[2 * kb    ][0], sS[2 * kb    ][1]);
                    a[1] = pack_h2(sS[2 * kb    ][2], sS[2 * kb    ][3]);
                    a[2] = pack_h2(sS[2 * kb + 1][0], sS[2 * kb + 1][1]);
                    a[3] = pack_h2(sS[2 * kb + 1][2], sS[2 * kb + 1][3]);
                    #pragma unroll
                    for (int hb = 0; hb < 8; hb++) {
                        const __half* vrow = vp + (hb * 8 + r) * 64;
                        uint2 bv = *(const uint2*)&vrow[(((2 * kb + cc) ^ rx) << 3) + hoff];
                        mma_f16(o[hb], a, bv.x, bv.y);
                    }
                }
            }
            bi = (bi + 1) & 3;
        }
    }

    lR  += __shfl_xor_sync(0xffffffffu, lR, 1);
    lR  += __shfl_xor_sync(0xffffffffu, lR, 2);
    lR8 += __shfl_xor_sync(0xffffffffu, lR8, 1);
    lR8 += __shfl_xor_sync(0xffffffffu, lR8, 2);

    const size_t pr  = (size_t)(s * BB + b) * TT + rowg;
    const size_t pr8 = pr + 8;
    #pragma unroll
    for (int hb = 0; hb < 8; hb++) {
        *(float2*)&g_pO[pr  * HH + hb * 8 + 2 * c] = make_float2(o[hb][0], o[hb][1]);
        *(float2*)&g_pO[pr8 * HH + hb * 8 + 2 * c] = make_float2(o[hb][2], o[hb][3]);
    }
    if (c == 0) {
        g_pl[pr]  = lR;
        g_pl[pr8] = lR8;
    }
}

// ---------------------------------------------------------------------------
// Kernel 3: merge the four kv-splits (unit weights). 2 quads per thread (ILP).
// ---------------------------------------------------------------------------
#define CHALF (BT * HH / 8)   // 131072 quads per half

__global__ __launch_bounds__(256) void combine_kernel(float* __restrict__ out)
{
    const int gid0 = blockIdx.x * 256 + threadIdx.x;

    #pragma unroll
    for (int hh = 0; hh < 2; hh++) {
        const int gid  = gid0 + hh * CHALF;
        const int rowg = gid >> 4;
        const int col  = (gid & 15) * 4;

        float denom = 0.0f;
        #pragma unroll
        for (int sp = 0; sp < NSPLIT; sp++)
            denom += g_pl[sp * BT + rowg];
        const float inv = 1.0f / denom;

        float4 acc = make_float4(0.f, 0.f, 0.f, 0.f);
        #pragma unroll
        for (int sp = 0; sp < NSPLIT; sp++) {
            float4 O = *(const float4*)&g_pO[((size_t)sp * BT + rowg) * HH + col];
            acc.x += O.x;
            acc.y += O.y;
            acc.z += O.z;
            acc.w += O.w;
        }
        acc.x *= inv; acc.y *= inv; acc.z *= inv; acc.w *= inv;
        *(float4*)&out[(size_t)rowg * HH + col] = acc;
    }
}

// ---------------------------------------------------------------------------
extern "C" void kernel_launch(void* const* d_in, const int* in_sizes, int n_in,
                              void* d_out, int out_size)
{
    const float* x  = (const float*)d_in[0];
    const float* Wq = (const float*)d_in[1];
    const float* Wk = (const float*)d_in[2];
    const float* Wv = (const float*)d_in[3];
    float* out = (float*)d_out;

    const int attn_smem = 4 * 16384;            // 64 KB (4-stage pipeline)
    const int qkv_smem  = 2 * (int)QKV_STAGE_B; // 86016 B
    cudaFuncSetAttribute(attn_kernel, cudaFuncAttributeMaxDynamicSharedMemorySize,
                         attn_smem);
    cudaFuncSetAttribute(qkv_mma, cudaFuncAttributeMaxDynamicSharedMemorySize,
                         qkv_smem);

    prep_w<<<(DD * 192 + 255) / 256, 256>>>(Wq, Wk, Wv);
    qkv_mma<<<(BT / 128) * 2, 256, qkv_smem>>>(x);
    attn_kernel<<<32 * BB * NSPLIT, 256, attn_smem>>>();
    combine_kernel<<<CHALF / 256, 256>>>(out);
}